// round 2
// baseline (speedup 1.0000x reference)
#include <cuda_runtime.h>
#include <cstdint>
#include <cstddef>

// ---------------- problem constants ----------------
static constexpr int GQ   = 8;
static constexpr int HDIM = 4096;
static constexpr int IDIM = 1536;
static constexpr int MTOT = 16384;
static constexpr int MG   = MTOT / GQ;        // 2048

// ---------------- tiling ----------------
static constexpr int TILE_M = 128;            // rows per CTA
static constexpr int TILE_J = 128;            // output cols per CTA
static constexpr int BROWS  = 2 * TILE_J;     // 256 w-rows (gate/up interleaved)
static constexpr int TILE_K = 32;
static constexpr int STAGES = 4;
static constexpr int NITER  = HDIM / TILE_K;  // 128
static constexpr int MT     = MG / TILE_M;    // 16
static constexpr int NT     = IDIM / TILE_J;  // 12

static constexpr int A_BYTES     = TILE_M * TILE_K * 4;   // 16 KB
static constexpr int B_BYTES     = BROWS  * TILE_K * 4;   // 32 KB
static constexpr int STAGE_BYTES = A_BYTES + B_BYTES;     // 48 KB
static constexpr int SMEM_TOTAL  = STAGES * STAGE_BYTES;  // 192 KB
static constexpr int THREADS     = 256;                   // 8 warps: 2m x 4n

// ---------------- PTX helpers (base sm_103 ONLY: no tcgen05) ----------------
__device__ __forceinline__ uint32_t smem_u32(const void* p) {
    uint32_t a;
    asm("{ .reg .u64 t; cvta.to.shared.u64 t, %1; cvt.u32.u64 %0, t; }" : "=r"(a) : "l"(p));
    return a;
}
__device__ __forceinline__ void cp_async16(uint32_t dst, const void* src) {
    asm volatile("cp.async.cg.shared.global [%0], [%1], 16;" :: "r"(dst), "l"(src));
}
__device__ __forceinline__ void cp_commit() {
    asm volatile("cp.async.commit_group;" ::: "memory");
}
__device__ __forceinline__ void cp_wait2() {
    asm volatile("cp.async.wait_group 2;" ::: "memory");
}
__device__ __forceinline__ void ldsm4(uint32_t* r, uint32_t addr) {
    asm volatile("ldmatrix.sync.aligned.m8n8.x4.shared.b16 {%0,%1,%2,%3}, [%4];"
                 : "=r"(r[0]), "=r"(r[1]), "=r"(r[2]), "=r"(r[3]) : "r"(addr));
}
__device__ __forceinline__ void cvt_tf32(uint32_t& r) {
    asm volatile("{ .reg .f32 t; mov.b32 t, %0; cvt.rna.tf32.f32 %0, t; }" : "+r"(r));
}
__device__ __forceinline__ void mma8(float* d, const uint32_t* a, uint32_t b0, uint32_t b1) {
    asm volatile(
        "mma.sync.aligned.m16n8k8.row.col.f32.tf32.tf32.f32 "
        "{%0,%1,%2,%3}, {%4,%5,%6,%7}, {%8,%9}, {%0,%1,%2,%3};"
        : "+f"(d[0]), "+f"(d[1]), "+f"(d[2]), "+f"(d[3])
        : "r"(a[0]), "r"(a[1]), "r"(a[2]), "r"(a[3]), "r"(b0), "r"(b1));
}

__device__ __forceinline__ float silu_mul(float g, float u) {
    return g * u / (1.0f + __expf(-g));
}

// ---------------- fused grouped GEMM + SwiGLU (Ampere-style, tf32) ----------------
__global__ void __launch_bounds__(THREADS, 1)
swiglu_kernel(const float* __restrict__ x, const float* __restrict__ w,
              float* __restrict__ out) {
    extern __shared__ char smem[];
    const uint32_t sb = smem_u32(smem);

    const int tid  = threadIdx.x;
    const int lane = tid & 31;
    const int wid  = tid >> 5;
    const int wm   = wid >> 2;   // 0..1
    const int wn   = wid & 3;    // 0..3

    const int bx = blockIdx.x;
    const int g  = bx / (MT * NT);
    const int r2 = bx % (MT * NT);
    const int mt = r2 / NT;
    const int nt = r2 % NT;

    const size_t m0 = (size_t)g * MG + (size_t)mt * TILE_M;
    const int    n0 = nt * TILE_J;

    const float* Ax = x + m0 * HDIM;
    const float* Wg = w + ((size_t)g * (2 * IDIM) + (size_t)n0) * HDIM;
    // up rows live at +IDIM*HDIM elements from the matching gate row

    // ---- per-thread cp.async descriptors ----
    // A tile: 128 rows x 32 k, blocks (m8, k4) of 8x16B rows, phys row = (m&7)^kseg
    uint32_t dA[4], oA[4];
    #pragma unroll
    for (int t = 0; t < 4; ++t) {
        const int c = tid + THREADS * t;     // 0..1023
        const int m = c >> 3, s = c & 7;
        dA[t] = (uint32_t)((((m >> 3) * 8 + s) << 7) + ((((m & 7) ^ s)) << 4));
        oA[t] = (uint32_t)(m * HDIM + s * 4);
    }
    // B tile: 256 interleaved rows (even=gate j, odd=up j)
    uint32_t dB[8], oB[8];
    #pragma unroll
    for (int t = 0; t < 8; ++t) {
        const int c  = tid + THREADS * t;    // 0..2047
        const int rr = c >> 3, s = c & 7;
        const int j  = rr >> 1;
        dB[t] = (uint32_t)(A_BYTES + (((rr >> 3) * 8 + s) << 7) + ((((rr & 7) ^ s)) << 4));
        oB[t] = (uint32_t)(j * HDIM + s * 4 + ((rr & 1) ? IDIM * HDIM : 0));
    }

    // ---- per-lane ldmatrix address terms ----
    const int quad = lane >> 3;
    const int row  = lane & 7;
    // A: quad -> (m-offset = quad&1, k-half = quad>>1)
    const uint32_t mterm0 = (uint32_t)(((wm * 8 + (quad & 1)) << 10) + 0);
    uint32_t ktA[4];
    #pragma unroll
    for (int ks = 0; ks < 4; ++ks) {
        const int kb = 2 * ks + (quad >> 1);
        ktA[ks] = (uint32_t)((kb << 7) + ((row ^ kb) << 4));
    }
    // B: quad -> (n-offset = quad>>1, k-sub = quad&1)
    const uint32_t nterm0 = (uint32_t)(A_BYTES + ((wn * 8 + (quad >> 1)) << 10));
    uint32_t ktB[4];
    #pragma unroll
    for (int ks = 0; ks < 4; ++ks) {
        const int kb = 2 * ks + (quad & 1);
        ktB[ks] = (uint32_t)((kb << 7) + ((row ^ kb) << 4));
    }

    float acc[128];
    #pragma unroll
    for (int i = 0; i < 128; ++i) acc[i] = 0.0f;

    // ---- prologue: fill STAGES-1 stages ----
    #pragma unroll
    for (int s = 0; s < STAGES - 1; ++s) {
        const uint32_t st = sb + (uint32_t)(s * STAGE_BYTES);
        const float* a = Ax + s * TILE_K;
        const float* b = Wg + s * TILE_K;
        #pragma unroll
        for (int t = 0; t < 4; ++t) cp_async16(st + dA[t], a + oA[t]);
        #pragma unroll
        for (int t = 0; t < 8; ++t) cp_async16(st + dB[t], b + oB[t]);
        cp_commit();
    }

    // ---- mainloop ----
    #pragma unroll 1
    for (int i = 0; i < NITER; ++i) {
        cp_wait2();
        __syncthreads();

        // refill slot (i+3)&3 == (i-1)&3 (computed last iter; safe after the sync)
        if (i + STAGES - 1 < NITER) {
            const int it = i + STAGES - 1;
            const uint32_t st = sb + (uint32_t)((it & 3) * STAGE_BYTES);
            const float* a = Ax + it * TILE_K;
            const float* b = Wg + it * TILE_K;
            #pragma unroll
            for (int t = 0; t < 4; ++t) cp_async16(st + dA[t], a + oA[t]);
            #pragma unroll
            for (int t = 0; t < 8; ++t) cp_async16(st + dB[t], b + oB[t]);
        }
        cp_commit();

        // compute on slot i&3
        const uint32_t st = sb + (uint32_t)((i & 3) * STAGE_BYTES);
        #pragma unroll
        for (int ks = 0; ks < 4; ++ks) {
            uint32_t afr[16], bfr[16];
            #pragma unroll
            for (int f = 0; f < 4; ++f)
                ldsm4(&afr[4 * f], st + mterm0 + (uint32_t)(f << 11) + ktA[ks]);
            #pragma unroll
            for (int gg = 0; gg < 4; ++gg)
                ldsm4(&bfr[4 * gg], st + nterm0 + (uint32_t)(gg << 11) + ktB[ks]);
            #pragma unroll
            for (int r = 0; r < 16; ++r) cvt_tf32(afr[r]);
            #pragma unroll
            for (int r = 0; r < 16; ++r) cvt_tf32(bfr[r]);
            #pragma unroll
            for (int f = 0; f < 4; ++f) {
                #pragma unroll
                for (int nf = 0; nf < 8; ++nf) {
                    const int bo = ((nf >> 1) << 2) + ((nf & 1) << 1);
                    mma8(&acc[(f * 8 + nf) * 4], &afr[4 * f], bfr[bo], bfr[bo + 1]);
                }
            }
        }
    }

    __syncthreads();

    // ---- epilogue: silu(gate)*up, direct global stores ----
    const int gid = lane >> 2;   // row within m16 frag
    const int tg  = lane & 3;    // col pair index
    #pragma unroll
    for (int f = 0; f < 4; ++f) {
        #pragma unroll
        for (int nf = 0; nf < 8; ++nf) {
            const float* c = &acc[(f * 8 + nf) * 4];
            const size_t mg1 = m0 + (size_t)(wm * 64 + f * 16 + gid);
            const int    jg  = n0 + wn * 32 + nf * 4 + tg;
            out[mg1 * IDIM + jg]       = silu_mul(c[0], c[1]);
            out[(mg1 + 8) * IDIM + jg] = silu_mul(c[2], c[3]);
        }
    }
}

// ---------------- launch ----------------
extern "C" void kernel_launch(void* const* d_in, const int* in_sizes, int n_in,
                              void* d_out, int out_size) {
    const float* x = (const float*)d_in[0];
    const float* w = (const float*)d_in[1];
    float* out = (float*)d_out;

    static bool attr_set = false;
    // cudaFuncSetAttribute is graph-capturable-safe to call every time; keep it simple.
    cudaFuncSetAttribute(swiglu_kernel,
                         cudaFuncAttributeMaxDynamicSharedMemorySize, SMEM_TOTAL);
    (void)attr_set;

    swiglu_kernel<<<GQ * MT * NT, THREADS, SMEM_TOTAL>>>(x, w, out);
}

// round 3
// speedup vs baseline: 1.0086x; 1.0086x over previous
#include <cuda_runtime.h>
#include <cstdint>
#include <cstddef>

// ---------------- problem constants ----------------
static constexpr int GQ   = 8;
static constexpr int HDIM = 4096;
static constexpr int IDIM = 1536;
static constexpr int MTOT = 16384;
static constexpr int MG   = MTOT / GQ;        // 2048

// ---------------- tiling ----------------
static constexpr int TILE_M = 128;            // rows per CTA
static constexpr int TILE_J = 128;            // output cols per CTA
static constexpr int BROWS  = 2 * TILE_J;     // 256 w-rows (gate/up interleaved)
static constexpr int TILE_K = 32;
static constexpr int STAGES = 4;
static constexpr int NITER  = HDIM / TILE_K;  // 128
static constexpr int MT     = MG / TILE_M;    // 16
static constexpr int NT     = IDIM / TILE_J;  // 12

static constexpr int A_BYTES     = TILE_M * TILE_K * 4;   // 16 KB
static constexpr int B_BYTES     = BROWS  * TILE_K * 4;   // 32 KB
static constexpr int STAGE_BYTES = A_BYTES + B_BYTES;     // 48 KB
static constexpr int SMEM_TOTAL  = STAGES * STAGE_BYTES;  // 192 KB
static constexpr int THREADS     = 512;                   // 16 warps: 4m x 4n

// ---------------- scratch: tf32-RNA-rounded copies of inputs ----------------
__device__ float g_x[(size_t)MTOT * HDIM];                 // 256 MB
__device__ float g_w[(size_t)GQ * 2 * IDIM * HDIM];        // 384 MB

// ---------------- PTX helpers (base sm_103: no tcgen05) ----------------
__device__ __forceinline__ uint32_t smem_u32(const void* p) {
    uint32_t a;
    asm("{ .reg .u64 t; cvta.to.shared.u64 t, %1; cvt.u32.u64 %0, t; }" : "=r"(a) : "l"(p));
    return a;
}
__device__ __forceinline__ void cp_async16(uint32_t dst, const void* src) {
    asm volatile("cp.async.cg.shared.global [%0], [%1], 16;" :: "r"(dst), "l"(src));
}
__device__ __forceinline__ void cp_commit() {
    asm volatile("cp.async.commit_group;" ::: "memory");
}
__device__ __forceinline__ void cp_wait2() {
    asm volatile("cp.async.wait_group 2;" ::: "memory");
}
__device__ __forceinline__ void ldsm4(uint32_t* r, uint32_t addr) {
    asm volatile("ldmatrix.sync.aligned.m8n8.x4.shared.b16 {%0,%1,%2,%3}, [%4];"
                 : "=r"(r[0]), "=r"(r[1]), "=r"(r[2]), "=r"(r[3]) : "r"(addr));
}
__device__ __forceinline__ void mma8(float* d, const uint32_t* a, uint32_t b0, uint32_t b1) {
    asm volatile(
        "mma.sync.aligned.m16n8k8.row.col.f32.tf32.tf32.f32 "
        "{%0,%1,%2,%3}, {%4,%5,%6,%7}, {%8,%9}, {%0,%1,%2,%3};"
        : "+f"(d[0]), "+f"(d[1]), "+f"(d[2]), "+f"(d[3])
        : "r"(a[0]), "r"(a[1]), "r"(a[2]), "r"(a[3]), "r"(b0), "r"(b1));
}
__device__ __forceinline__ float silu_mul(float g, float u) {
    return g * u / (1.0f + __expf(-g));
}

// ---------------- prepass: fp32 -> tf32 (round-to-nearest, unbiased) ----------------
__global__ void cvt_tf32_kernel(const float4* __restrict__ src, float4* __restrict__ dst, int n4) {
    int i = blockIdx.x * blockDim.x + threadIdx.x;
    const int stride = gridDim.x * blockDim.x;
    for (; i < n4; i += stride) {
        float4 v = src[i];
        uint32_t a, b, c, d;
        asm("cvt.rna.tf32.f32 %0, %1;" : "=r"(a) : "f"(v.x));
        asm("cvt.rna.tf32.f32 %0, %1;" : "=r"(b) : "f"(v.y));
        asm("cvt.rna.tf32.f32 %0, %1;" : "=r"(c) : "f"(v.z));
        asm("cvt.rna.tf32.f32 %0, %1;" : "=r"(d) : "f"(v.w));
        v.x = __uint_as_float(a); v.y = __uint_as_float(b);
        v.z = __uint_as_float(c); v.w = __uint_as_float(d);
        dst[i] = v;
    }
}

// ---------------- fused grouped GEMM + SwiGLU ----------------
__global__ void __launch_bounds__(THREADS, 1)
swiglu_kernel(const float* __restrict__ x, const float* __restrict__ w,
              float* __restrict__ out) {
    extern __shared__ char smem[];
    const uint32_t sb = smem_u32(smem);

    const int tid  = threadIdx.x;
    const int lane = tid & 31;
    const int wid  = tid >> 5;
    const int wm   = wid >> 2;   // 0..3 (32 m-rows each)
    const int wn   = wid & 3;    // 0..3 (64 B-cols each)

    const int bx = blockIdx.x;
    const int g  = bx / (MT * NT);
    const int r2 = bx % (MT * NT);
    const int mt = r2 / NT;
    const int nt = r2 % NT;

    const size_t m0 = (size_t)g * MG + (size_t)mt * TILE_M;
    const int    n0 = nt * TILE_J;

    const float* Ax = x + m0 * HDIM;
    const float* Wg = w + ((size_t)g * (2 * IDIM) + (size_t)n0) * HDIM;

    // ---- per-thread cp.async descriptors ----
    // A tile: phys addr = ((m>>3)*8+s)<<7 + ((m&7)^s)<<4, s = 16B k-seg
    uint32_t dA[2], oA[2];
    #pragma unroll
    for (int t = 0; t < 2; ++t) {
        const int c = tid + THREADS * t;     // 0..1023
        const int m = c >> 3, s = c & 7;
        dA[t] = (uint32_t)((((m >> 3) * 8 + s) << 7) + (((m & 7) ^ s) << 4));
        oA[t] = (uint32_t)(m * HDIM + s * 4);
    }
    // B tile: 256 interleaved rows (even=gate j, odd=up j)
    uint32_t dB[4], oB[4];
    #pragma unroll
    for (int t = 0; t < 4; ++t) {
        const int c  = tid + THREADS * t;    // 0..2047
        const int rr = c >> 3, s = c & 7;
        const int j  = rr >> 1;
        dB[t] = (uint32_t)(A_BYTES + (((rr >> 3) * 8 + s) << 7) + (((rr & 7) ^ s) << 4));
        oB[t] = (uint32_t)(j * HDIM + s * 4 + ((rr & 1) ? IDIM * HDIM : 0));
    }

    // ---- per-lane ldmatrix address terms (layout verified in R2) ----
    const int quad = lane >> 3;
    const int row  = lane & 7;
    // A: quad -> (m 8-block = quad&1, k-half = quad>>1); warp m-base = wm*32 rows
    const uint32_t mterm0 = (uint32_t)(((wm * 4 + (quad & 1)) << 10));
    uint32_t ktA[4];
    #pragma unroll
    for (int ks = 0; ks < 4; ++ks) {
        const int kb = 2 * ks + (quad >> 1);
        ktA[ks] = (uint32_t)((kb << 7) + ((row ^ kb) << 4));
    }
    // B: quad -> (n 8-block = quad>>1, k-sub = quad&1); warp n-base = wn*64 B-rows
    const uint32_t nterm0 = (uint32_t)(A_BYTES + ((wn * 8 + (quad >> 1)) << 10));
    uint32_t ktB[4];
    #pragma unroll
    for (int ks = 0; ks < 4; ++ks) {
        const int kb = 2 * ks + (quad & 1);
        ktB[ks] = (uint32_t)((kb << 7) + ((row ^ kb) << 4));
    }

    float acc[64];
    #pragma unroll
    for (int i = 0; i < 64; ++i) acc[i] = 0.0f;

    // ---- prologue ----
    #pragma unroll
    for (int s = 0; s < STAGES - 1; ++s) {
        const uint32_t st = sb + (uint32_t)(s * STAGE_BYTES);
        const float* a = Ax + s * TILE_K;
        const float* b = Wg + s * TILE_K;
        #pragma unroll
        for (int t = 0; t < 2; ++t) cp_async16(st + dA[t], a + oA[t]);
        #pragma unroll
        for (int t = 0; t < 4; ++t) cp_async16(st + dB[t], b + oB[t]);
        cp_commit();
    }

    // ---- mainloop ----
    #pragma unroll 1
    for (int i = 0; i < NITER; ++i) {
        cp_wait2();
        __syncthreads();

        if (i + STAGES - 1 < NITER) {
            const int it = i + STAGES - 1;
            const uint32_t st = sb + (uint32_t)((it & 3) * STAGE_BYTES);
            const float* a = Ax + it * TILE_K;
            const float* b = Wg + it * TILE_K;
            #pragma unroll
            for (int t = 0; t < 2; ++t) cp_async16(st + dA[t], a + oA[t]);
            #pragma unroll
            for (int t = 0; t < 4; ++t) cp_async16(st + dB[t], b + oB[t]);
        }
        cp_commit();

        const uint32_t st = sb + (uint32_t)((i & 3) * STAGE_BYTES);
        #pragma unroll
        for (int ks = 0; ks < 4; ++ks) {
            uint32_t afr[8], bfr[16];
            #pragma unroll
            for (int f = 0; f < 2; ++f)
                ldsm4(&afr[4 * f], st + mterm0 + (uint32_t)(f << 11) + ktA[ks]);
            #pragma unroll
            for (int gg = 0; gg < 4; ++gg)
                ldsm4(&bfr[4 * gg], st + nterm0 + (uint32_t)(gg << 11) + ktB[ks]);
            #pragma unroll
            for (int f = 0; f < 2; ++f) {
                #pragma unroll
                for (int nf = 0; nf < 8; ++nf) {
                    const int bo = ((nf >> 1) << 2) + ((nf & 1) << 1);
                    mma8(&acc[(f * 8 + nf) * 4], &afr[4 * f], bfr[bo], bfr[bo + 1]);
                }
            }
        }
    }

    __syncthreads();

    // ---- epilogue: silu(gate)*up, direct global stores ----
    const int gid = lane >> 2;
    const int tg  = lane & 3;
    #pragma unroll
    for (int f = 0; f < 2; ++f) {
        #pragma unroll
        for (int nf = 0; nf < 8; ++nf) {
            const float* c = &acc[(f * 8 + nf) * 4];
            const size_t mg1 = m0 + (size_t)(wm * 32 + f * 16 + gid);
            const int    jg  = n0 + wn * 32 + nf * 4 + tg;
            out[mg1 * IDIM + jg]       = silu_mul(c[0], c[1]);
            out[(mg1 + 8) * IDIM + jg] = silu_mul(c[2], c[3]);
        }
    }
}

// ---------------- launch ----------------
extern "C" void kernel_launch(void* const* d_in, const int* in_sizes, int n_in,
                              void* d_out, int out_size) {
    const float* x = (const float*)d_in[0];
    const float* w = (const float*)d_in[1];
    float* out = (float*)d_out;

    void* px = nullptr;
    void* pw = nullptr;
    cudaGetSymbolAddress(&px, g_x);
    cudaGetSymbolAddress(&pw, g_w);

    cvt_tf32_kernel<<<2048, 256>>>((const float4*)x, (float4*)px,
                                   (int)(((size_t)MTOT * HDIM) / 4));
    cvt_tf32_kernel<<<2048, 256>>>((const float4*)w, (float4*)pw,
                                   (int)(((size_t)GQ * 2 * IDIM * HDIM) / 4));

    cudaFuncSetAttribute(swiglu_kernel,
                         cudaFuncAttributeMaxDynamicSharedMemorySize, SMEM_TOTAL);
    swiglu_kernel<<<GQ * MT * NT, THREADS, SMEM_TOTAL>>>((const float*)px, (const float*)pw, out);
}

// round 4
// speedup vs baseline: 1.0932x; 1.0839x over previous
#include <cuda_runtime.h>
#include <cstdint>
#include <cstddef>

// ---------------- problem constants ----------------
static constexpr int GQ   = 8;
static constexpr int HDIM = 4096;
static constexpr int IDIM = 1536;
static constexpr int MTOT = 16384;
static constexpr int MG   = MTOT / GQ;        // 2048

// ---------------- tiling ----------------
static constexpr int TILE_M = 128;            // rows per CTA
static constexpr int TILE_J = 128;            // output cols per CTA
static constexpr int BROWS  = 2 * TILE_J;     // 256 w-rows (gate/up interleaved)
static constexpr int TILE_K = 32;
static constexpr int STAGES = 4;
static constexpr int NITER  = HDIM / TILE_K;  // 128
static constexpr int MT     = MG / TILE_M;    // 16
static constexpr int NT     = IDIM / TILE_J;  // 12

static constexpr int A_BYTES     = TILE_M * TILE_K * 4;   // 16 KB
static constexpr int B_BYTES     = BROWS  * TILE_K * 4;   // 32 KB
static constexpr int STAGE_BYTES = A_BYTES + B_BYTES;     // 48 KB
static constexpr int SMEM_TOTAL  = STAGES * STAGE_BYTES;  // 192 KB
static constexpr int THREADS     = 256;                   // 8 warps: 2m x 4n

// ---------------- scratch: tf32-RNA-rounded copies of inputs ----------------
__device__ float g_x[(size_t)MTOT * HDIM];                 // 256 MB
__device__ float g_w[(size_t)GQ * 2 * IDIM * HDIM];        // 384 MB

// ---------------- PTX helpers (base sm_103: no tcgen05) ----------------
__device__ __forceinline__ uint32_t smem_u32(const void* p) {
    uint32_t a;
    asm("{ .reg .u64 t; cvta.to.shared.u64 t, %1; cvt.u32.u64 %0, t; }" : "=r"(a) : "l"(p));
    return a;
}
__device__ __forceinline__ void cp_async16(uint32_t dst, const void* src) {
    asm volatile("cp.async.cg.shared.global [%0], [%1], 16;" :: "r"(dst), "l"(src));
}
__device__ __forceinline__ void cp_commit() {
    asm volatile("cp.async.commit_group;" ::: "memory");
}
__device__ __forceinline__ void cp_wait1() {
    asm volatile("cp.async.wait_group 1;" ::: "memory");
}
__device__ __forceinline__ void ldsm4(uint32_t* r, uint32_t addr) {
    asm volatile("ldmatrix.sync.aligned.m8n8.x4.shared.b16 {%0,%1,%2,%3}, [%4];"
                 : "=r"(r[0]), "=r"(r[1]), "=r"(r[2]), "=r"(r[3]) : "r"(addr));
}
__device__ __forceinline__ void mma8(float* d, const uint32_t* a, uint32_t b0, uint32_t b1) {
    asm volatile(
        "mma.sync.aligned.m16n8k8.row.col.f32.tf32.tf32.f32 "
        "{%0,%1,%2,%3}, {%4,%5,%6,%7}, {%8,%9}, {%0,%1,%2,%3};"
        : "+f"(d[0]), "+f"(d[1]), "+f"(d[2]), "+f"(d[3])
        : "r"(a[0]), "r"(a[1]), "r"(a[2]), "r"(a[3]), "r"(b0), "r"(b1));
}
__device__ __forceinline__ float silu_mul(float g, float u) {
    return g * u / (1.0f + __expf(-g));
}

// ---------------- prepass: fp32 -> tf32 (round-to-nearest, unbiased) ----------------
__global__ void cvt_tf32_kernel(const float4* __restrict__ src, float4* __restrict__ dst, int n4) {
    int i = blockIdx.x * blockDim.x + threadIdx.x;
    const int stride = gridDim.x * blockDim.x;
    for (; i < n4; i += stride) {
        float4 v = src[i];
        uint32_t a, b, c, d;
        asm("cvt.rna.tf32.f32 %0, %1;" : "=r"(a) : "f"(v.x));
        asm("cvt.rna.tf32.f32 %0, %1;" : "=r"(b) : "f"(v.y));
        asm("cvt.rna.tf32.f32 %0, %1;" : "=r"(c) : "f"(v.z));
        asm("cvt.rna.tf32.f32 %0, %1;" : "=r"(d) : "f"(v.w));
        v.x = __uint_as_float(a); v.y = __uint_as_float(b);
        v.z = __uint_as_float(c); v.w = __uint_as_float(d);
        dst[i] = v;
    }
}

// ---------------- fused grouped GEMM + SwiGLU ----------------
__global__ void __launch_bounds__(THREADS, 1)
swiglu_kernel(const float* __restrict__ x, const float* __restrict__ w,
              float* __restrict__ out) {
    extern __shared__ char smem[];
    const uint32_t sb = smem_u32(smem);

    const int tid  = threadIdx.x;
    const int lane = tid & 31;
    const int wid  = tid >> 5;
    const int wm   = wid >> 2;   // 0..1 (64 m-rows each)
    const int wn   = wid & 3;    // 0..3 (64 B-rows each)

    const int bx = blockIdx.x;
    const int g  = bx / (MT * NT);
    const int r2 = bx % (MT * NT);
    const int mt = r2 / NT;
    const int nt = r2 % NT;

    const size_t m0 = (size_t)g * MG + (size_t)mt * TILE_M;
    const int    n0 = nt * TILE_J;

    const float* Ax = x + m0 * HDIM;
    const float* Wg = w + ((size_t)g * (2 * IDIM) + (size_t)n0) * HDIM;

    // ---- per-thread cp.async descriptors (layout verified R2) ----
    uint32_t dA[4], oA[4];
    #pragma unroll
    for (int t = 0; t < 4; ++t) {
        const int c = tid + THREADS * t;     // 0..1023
        const int m = c >> 3, s = c & 7;
        dA[t] = (uint32_t)((((m >> 3) * 8 + s) << 7) + (((m & 7) ^ s) << 4));
        oA[t] = (uint32_t)(m * HDIM + s * 4);
    }
    uint32_t dB[8], oB[8];
    #pragma unroll
    for (int t = 0; t < 8; ++t) {
        const int c  = tid + THREADS * t;    // 0..2047
        const int rr = c >> 3, s = c & 7;
        const int j  = rr >> 1;
        dB[t] = (uint32_t)(A_BYTES + (((rr >> 3) * 8 + s) << 7) + (((rr & 7) ^ s) << 4));
        oB[t] = (uint32_t)(j * HDIM + s * 4 + ((rr & 1) ? IDIM * HDIM : 0));
    }

    // ---- per-lane ldmatrix terms (verified R2) ----
    const int quad = lane >> 3;
    const int row  = lane & 7;
    const uint32_t mterm0 = (uint32_t)(((wm * 8 + (quad & 1)) << 10));
    uint32_t ktA[4];
    #pragma unroll
    for (int ks = 0; ks < 4; ++ks) {
        const int kb = 2 * ks + (quad >> 1);
        ktA[ks] = (uint32_t)((kb << 7) + ((row ^ kb) << 4));
    }
    const uint32_t nterm0 = (uint32_t)(A_BYTES + ((wn * 8 + (quad >> 1)) << 10));
    uint32_t ktB[4];
    #pragma unroll
    for (int ks = 0; ks < 4; ++ks) {
        const int kb = 2 * ks + (quad & 1);
        ktB[ks] = (uint32_t)((kb << 7) + ((row ^ kb) << 4));
    }

    float acc[128];
    #pragma unroll
    for (int i = 0; i < 128; ++i) acc[i] = 0.0f;

    // ---- prologue: fill stages 0..2 ----
    #pragma unroll
    for (int s = 0; s < STAGES - 1; ++s) {
        const uint32_t st = sb + (uint32_t)(s * STAGE_BYTES);
        const float* a = Ax + s * TILE_K;
        const float* b = Wg + s * TILE_K;
        #pragma unroll
        for (int t = 0; t < 4; ++t) cp_async16(st + dA[t], a + oA[t]);
        #pragma unroll
        for (int t = 0; t < 8; ++t) cp_async16(st + dB[t], b + oB[t]);
        cp_commit();
    }

    // ---- bootstrap: fragments for (iter 0, ks 0) into buffer 0 ----
    uint32_t afr[2][16], bfr[2][16];
    cp_wait1();              // stages 0,1 resident (own warp)
    __syncthreads();         // cross-warp visibility
    {
        const uint32_t st = sb;
        #pragma unroll
        for (int f = 0; f < 4; ++f)
            ldsm4(&afr[0][4 * f], st + mterm0 + (uint32_t)(f << 11) + ktA[0]);
        #pragma unroll
        for (int gg = 0; gg < 4; ++gg)
            ldsm4(&bfr[0][4 * gg], st + nterm0 + (uint32_t)(gg << 11) + ktB[0]);
    }

    // ---- mainloop: register-double-buffered fragment pipeline ----
    #pragma unroll 1
    for (int i = 0; i < NITER; ++i) {
        cp_wait1();          // stages <= i+1 resident (own warp)
        __syncthreads();     // cross-warp stage i+1 visible; stage i-1 reads done
        if (i + STAGES - 1 < NITER) {
            const int it = i + STAGES - 1;
            const uint32_t stw = sb + (uint32_t)((it & 3) * STAGE_BYTES);
            const float* a = Ax + it * TILE_K;
            const float* b = Wg + it * TILE_K;
            #pragma unroll
            for (int t = 0; t < 4; ++t) cp_async16(stw + dA[t], a + oA[t]);
            #pragma unroll
            for (int t = 0; t < 8; ++t) cp_async16(stw + dB[t], b + oB[t]);
        }
        cp_commit();

        const uint32_t st  = sb + (uint32_t)((i & 3) * STAGE_BYTES);
        const uint32_t stn = sb + (uint32_t)(((i + 1) & 3) * STAGE_BYTES);
        #pragma unroll
        for (int ks = 0; ks < 4; ++ks) {
            const int cur = ks & 1;
            const int nxt = cur ^ 1;
            // prefetch next fragments (ks+1 of this stage, or ks0 of next stage)
            const uint32_t pst = (ks < 3) ? st : stn;
            const int pks = (ks < 3) ? (ks + 1) : 0;
            #pragma unroll
            for (int f = 0; f < 4; ++f)
                ldsm4(&afr[nxt][4 * f], pst + mterm0 + (uint32_t)(f << 11) + ktA[pks]);
            #pragma unroll
            for (int gg = 0; gg < 4; ++gg)
                ldsm4(&bfr[nxt][4 * gg], pst + nterm0 + (uint32_t)(gg << 11) + ktB[pks]);
            // MMAs on current buffer (independent of the prefetch above)
            #pragma unroll
            for (int f = 0; f < 4; ++f) {
                #pragma unroll
                for (int nf = 0; nf < 8; ++nf) {
                    const int bo = ((nf >> 1) << 2) + ((nf & 1) << 1);
                    mma8(&acc[(f * 8 + nf) * 4], &afr[cur][4 * f],
                         bfr[cur][bo], bfr[cur][bo + 1]);
                }
            }
        }
    }

    __syncthreads();

    // ---- epilogue: silu(gate)*up, direct global stores ----
    const int gid = lane >> 2;
    const int tg  = lane & 3;
    #pragma unroll
    for (int f = 0; f < 4; ++f) {
        #pragma unroll
        for (int nf = 0; nf < 8; ++nf) {
            const float* c = &acc[(f * 8 + nf) * 4];
            const size_t mg1 = m0 + (size_t)(wm * 64 + f * 16 + gid);
            const int    jg  = n0 + wn * 32 + nf * 4 + tg;
            out[mg1 * IDIM + jg]       = silu_mul(c[0], c[1]);
            out[(mg1 + 8) * IDIM + jg] = silu_mul(c[2], c[3]);
        }
    }
}

// ---------------- launch ----------------
extern "C" void kernel_launch(void* const* d_in, const int* in_sizes, int n_in,
                              void* d_out, int out_size) {
    const float* x = (const float*)d_in[0];
    const float* w = (const float*)d_in[1];
    float* out = (float*)d_out;

    void* px = nullptr;
    void* pw = nullptr;
    cudaGetSymbolAddress(&px, g_x);
    cudaGetSymbolAddress(&pw, g_w);

    cvt_tf32_kernel<<<2048, 256>>>((const float4*)x, (float4*)px,
                                   (int)(((size_t)MTOT * HDIM) / 4));
    cvt_tf32_kernel<<<2048, 256>>>((const float4*)w, (float4*)pw,
                                   (int)(((size_t)GQ * 2 * IDIM * HDIM) / 4));

    cudaFuncSetAttribute(swiglu_kernel,
                         cudaFuncAttributeMaxDynamicSharedMemorySize, SMEM_TOTAL);
    swiglu_kernel<<<GQ * MT * NT, THREADS, SMEM_TOTAL>>>((const float*)px, (const float*)pw, out);
}

// round 5
// speedup vs baseline: 1.1182x; 1.0228x over previous
#include <cuda_runtime.h>
#include <cstdint>
#include <cstddef>

// ---------------- problem constants ----------------
static constexpr int GQ   = 8;
static constexpr int HDIM = 4096;
static constexpr int IDIM = 1536;
static constexpr int MTOT = 16384;
static constexpr int MG   = MTOT / GQ;        // 2048

// ---------------- tiling ----------------
static constexpr int TILE_M = 128;            // rows per CTA
static constexpr int TILE_J = 96;             // output cols per CTA
static constexpr int BROWS  = 2 * TILE_J;     // 192 w-rows (gate/up interleaved)
static constexpr int TILE_K = 32;
static constexpr int STAGES = 4;
static constexpr int NITER  = HDIM / TILE_K;  // 128
static constexpr int MT     = MG / TILE_M;    // 16
static constexpr int NT     = IDIM / TILE_J;  // 16

static constexpr int A_BYTES     = TILE_M * TILE_K * 4;   // 16 KB
static constexpr int B_BYTES     = BROWS  * TILE_K * 4;   // 24 KB
static constexpr int STAGE_BYTES = A_BYTES + B_BYTES;     // 40 KB
static constexpr int SMEM_TOTAL  = STAGES * STAGE_BYTES;  // 160 KB
static constexpr int THREADS     = 384;                   // 12 warps: 2m x 6n

// ---------------- scratch: tf32-RNA-rounded copies of inputs ----------------
__device__ float g_x[(size_t)MTOT * HDIM];                 // 256 MB
__device__ float g_w[(size_t)GQ * 2 * IDIM * HDIM];        // 384 MB

// ---------------- PTX helpers (base sm_103: no tcgen05) ----------------
__device__ __forceinline__ uint32_t smem_u32(const void* p) {
    uint32_t a;
    asm("{ .reg .u64 t; cvta.to.shared.u64 t, %1; cvt.u32.u64 %0, t; }" : "=r"(a) : "l"(p));
    return a;
}
__device__ __forceinline__ void cp_async16(uint32_t dst, const void* src) {
    asm volatile("cp.async.cg.shared.global [%0], [%1], 16;" :: "r"(dst), "l"(src));
}
__device__ __forceinline__ void cp_commit() {
    asm volatile("cp.async.commit_group;" ::: "memory");
}
__device__ __forceinline__ void cp_wait1() {
    asm volatile("cp.async.wait_group 1;" ::: "memory");
}
__device__ __forceinline__ void ldsm4(uint32_t* r, uint32_t addr) {
    asm volatile("ldmatrix.sync.aligned.m8n8.x4.shared.b16 {%0,%1,%2,%3}, [%4];"
                 : "=r"(r[0]), "=r"(r[1]), "=r"(r[2]), "=r"(r[3]) : "r"(addr));
}
__device__ __forceinline__ void mma8(float* d, const uint32_t* a, uint32_t b0, uint32_t b1) {
    asm volatile(
        "mma.sync.aligned.m16n8k8.row.col.f32.tf32.tf32.f32 "
        "{%0,%1,%2,%3}, {%4,%5,%6,%7}, {%8,%9}, {%0,%1,%2,%3};"
        : "+f"(d[0]), "+f"(d[1]), "+f"(d[2]), "+f"(d[3])
        : "r"(a[0]), "r"(a[1]), "r"(a[2]), "r"(a[3]), "r"(b0), "r"(b1));
}
__device__ __forceinline__ float silu_mul(float g, float u) {
    return g * u / (1.0f + __expf(-g));
}

// ---------------- prepass: fp32 -> tf32 (round-to-nearest, unbiased) ----------------
__global__ void cvt_tf32_kernel(const float4* __restrict__ src, float4* __restrict__ dst, int n4) {
    int i = blockIdx.x * blockDim.x + threadIdx.x;
    const int stride = gridDim.x * blockDim.x;
    for (; i < n4; i += stride) {
        float4 v = src[i];
        uint32_t a, b, c, d;
        asm("cvt.rna.tf32.f32 %0, %1;" : "=r"(a) : "f"(v.x));
        asm("cvt.rna.tf32.f32 %0, %1;" : "=r"(b) : "f"(v.y));
        asm("cvt.rna.tf32.f32 %0, %1;" : "=r"(c) : "f"(v.z));
        asm("cvt.rna.tf32.f32 %0, %1;" : "=r"(d) : "f"(v.w));
        v.x = __uint_as_float(a); v.y = __uint_as_float(b);
        v.z = __uint_as_float(c); v.w = __uint_as_float(d);
        dst[i] = v;
    }
}

// ---------------- fused grouped GEMM + SwiGLU ----------------
__global__ void __launch_bounds__(THREADS, 1)
swiglu_kernel(const float* __restrict__ x, const float* __restrict__ w,
              float* __restrict__ out) {
    extern __shared__ char smem[];
    const uint32_t sb = smem_u32(smem);

    const int tid  = threadIdx.x;
    const int lane = tid & 31;
    const int wid  = tid >> 5;
    const int wm   = wid / 6;        // 0..1 (64 m-rows each)
    const int wn   = wid - 6 * wm;   // 0..5 (32 B-rows = 16 out-cols each)

    const int bx = blockIdx.x;
    const int g  = bx / (MT * NT);
    const int r2 = bx % (MT * NT);
    const int mt = r2 / NT;
    const int nt = r2 % NT;

    const size_t m0 = (size_t)g * MG + (size_t)mt * TILE_M;
    const int    n0 = nt * TILE_J;

    const float* Ax = x + m0 * HDIM;
    const float* Wg = w + ((size_t)g * (2 * IDIM) + (size_t)n0) * HDIM;

    // ---- per-thread cp.async descriptors (physical layout verified R2) ----
    // A: 1024 16B-segs; threads 0..255 take a 3rd seg
    uint32_t dA[3], oA[3];
    #pragma unroll
    for (int t = 0; t < 3; ++t) {
        const int c = tid + THREADS * t;     // 0..1151 (valid < 1024)
        const int m = (c < 1024) ? (c >> 3) : 0;
        const int s = c & 7;
        dA[t] = (uint32_t)((((m >> 3) * 8 + s) << 7) + (((m & 7) ^ s) << 4));
        oA[t] = (uint32_t)(m * HDIM + s * 4);
    }
    const bool a3 = (tid < 1024 - 2 * THREADS);  // tid < 256
    // B: 1536 16B-segs, exactly 4 per thread; rows interleaved gate/up
    uint32_t dB[4], oB[4];
    #pragma unroll
    for (int t = 0; t < 4; ++t) {
        const int c  = tid + THREADS * t;    // 0..1535
        const int rr = c >> 3, s = c & 7;
        const int j  = rr >> 1;
        dB[t] = (uint32_t)(A_BYTES + (((rr >> 3) * 8 + s) << 7) + (((rr & 7) ^ s) << 4));
        oB[t] = (uint32_t)(j * HDIM + s * 4 + ((rr & 1) ? IDIM * HDIM : 0));
    }

    // ---- per-lane ldmatrix terms (verified R2) ----
    const int quad = lane >> 3;
    const int row  = lane & 7;
    const uint32_t mterm0 = (uint32_t)((wm * 8 + (quad & 1)) << 10);
    uint32_t ktA[4];
    #pragma unroll
    for (int ks = 0; ks < 4; ++ks) {
        const int kb = 2 * ks + (quad >> 1);
        ktA[ks] = (uint32_t)((kb << 7) + ((row ^ kb) << 4));
    }
    const uint32_t nterm0 = (uint32_t)(A_BYTES + ((wn * 4 + (quad >> 1)) << 10));
    uint32_t ktB[4];
    #pragma unroll
    for (int ks = 0; ks < 4; ++ks) {
        const int kb = 2 * ks + (quad & 1);
        ktB[ks] = (uint32_t)((kb << 7) + ((row ^ kb) << 4));
    }

    float acc[64];
    #pragma unroll
    for (int i = 0; i < 64; ++i) acc[i] = 0.0f;

    // ---- prologue: fill stages 0..2 ----
    #pragma unroll
    for (int s = 0; s < STAGES - 1; ++s) {
        const uint32_t st = sb + (uint32_t)(s * STAGE_BYTES);
        const float* a = Ax + s * TILE_K;
        const float* b = Wg + s * TILE_K;
        cp_async16(st + dA[0], a + oA[0]);
        cp_async16(st + dA[1], a + oA[1]);
        if (a3) cp_async16(st + dA[2], a + oA[2]);
        #pragma unroll
        for (int t = 0; t < 4; ++t) cp_async16(st + dB[t], b + oB[t]);
        cp_commit();
    }

    // ---- bootstrap: fragments for (iter 0, ks 0) into buffer 0 ----
    uint32_t afr[2][16], bfr[2][8];
    cp_wait1();
    __syncthreads();
    {
        const uint32_t st = sb;
        #pragma unroll
        for (int f = 0; f < 4; ++f)
            ldsm4(&afr[0][4 * f], st + mterm0 + (uint32_t)(f << 11) + ktA[0]);
        #pragma unroll
        for (int gg = 0; gg < 2; ++gg)
            ldsm4(&bfr[0][4 * gg], st + nterm0 + (uint32_t)(gg << 11) + ktB[0]);
    }

    // ---- mainloop ----
    #pragma unroll 1
    for (int i = 0; i < NITER; ++i) {
        cp_wait1();          // stages <= i+1 resident (own warp's copies)
        __syncthreads();     // cross-warp visibility; stage i-1 reads complete

        const uint32_t st  = sb + (uint32_t)((i & 3) * STAGE_BYTES);
        const uint32_t stn = sb + (uint32_t)(((i + 1) & 3) * STAGE_BYTES);

        #pragma unroll
        for (int ks = 0; ks < 4; ++ks) {
            const int cur = ks & 1;
            const int nxt = cur ^ 1;
            const uint32_t pst = (ks < 3) ? st : stn;
            const int pks = (ks < 3) ? (ks + 1) : 0;
            // prefetch next fragments into the other register buffer
            #pragma unroll
            for (int f = 0; f < 4; ++f)
                ldsm4(&afr[nxt][4 * f], pst + mterm0 + (uint32_t)(f << 11) + ktA[pks]);
            #pragma unroll
            for (int gg = 0; gg < 2; ++gg)
                ldsm4(&bfr[nxt][4 * gg], pst + nterm0 + (uint32_t)(gg << 11) + ktB[pks]);
            // MMAs on current buffer
            #pragma unroll
            for (int f = 0; f < 4; ++f) {
                #pragma unroll
                for (int nf = 0; nf < 4; ++nf) {
                    mma8(&acc[(f * 4 + nf) * 4], &afr[cur][4 * f],
                         bfr[cur][2 * nf], bfr[cur][2 * nf + 1]);
                }
            }
            // refill burst after the first MMA batch (tensor pipe already running)
            if (ks == 0) {
                if (i + STAGES - 1 < NITER) {
                    const int it = i + STAGES - 1;
                    const uint32_t stw = sb + (uint32_t)((it & 3) * STAGE_BYTES);
                    const float* a = Ax + it * TILE_K;
                    const float* b = Wg + it * TILE_K;
                    cp_async16(stw + dA[0], a + oA[0]);
                    cp_async16(stw + dA[1], a + oA[1]);
                    if (a3) cp_async16(stw + dA[2], a + oA[2]);
                    #pragma unroll
                    for (int t = 0; t < 4; ++t) cp_async16(stw + dB[t], b + oB[t]);
                }
                cp_commit();
            }
        }
    }

    __syncthreads();

    // ---- epilogue: silu(gate)*up, direct global stores ----
    const int gid = lane >> 2;
    const int tg  = lane & 3;
    #pragma unroll
    for (int f = 0; f < 4; ++f) {
        #pragma unroll
        for (int nf = 0; nf < 4; ++nf) {
            const float* c = &acc[(f * 4 + nf) * 4];
            const size_t mg1 = m0 + (size_t)(wm * 64 + f * 16 + gid);
            const int    jg  = n0 + wn * 16 + nf * 4 + tg;
            out[mg1 * IDIM + jg]       = silu_mul(c[0], c[1]);
            out[(mg1 + 8) * IDIM + jg] = silu_mul(c[2], c[3]);
        }
    }
}

// ---------------- launch ----------------
extern "C" void kernel_launch(void* const* d_in, const int* in_sizes, int n_in,
                              void* d_out, int out_size) {
    const float* x = (const float*)d_in[0];
    const float* w = (const float*)d_in[1];
    float* out = (float*)d_out;

    void* px = nullptr;
    void* pw = nullptr;
    cudaGetSymbolAddress(&px, g_x);
    cudaGetSymbolAddress(&pw, g_w);

    cvt_tf32_kernel<<<2048, 256>>>((const float4*)x, (float4*)px,
                                   (int)(((size_t)MTOT * HDIM) / 4));
    cvt_tf32_kernel<<<2048, 256>>>((const float4*)w, (float4*)pw,
                                   (int)(((size_t)GQ * 2 * IDIM * HDIM) / 4));

    cudaFuncSetAttribute(swiglu_kernel,
                         cudaFuncAttributeMaxDynamicSharedMemorySize, SMEM_TOTAL);
    swiglu_kernel<<<GQ * MT * NT, THREADS, SMEM_TOTAL>>>((const float*)px, (const float*)pw, out);
}

// round 6
// speedup vs baseline: 1.9367x; 1.7321x over previous
#include <cuda_runtime.h>
#include <cuda_fp16.h>
#include <cstdint>
#include <cstddef>

// ---------------- problem constants ----------------
static constexpr int GQ   = 8;
static constexpr int HDIM = 4096;
static constexpr int IDIM = 1536;
static constexpr int MTOT = 16384;
static constexpr int MG   = MTOT / GQ;        // 2048

// ---------------- tiling ----------------
static constexpr int TILE_M = 128;            // rows per CTA
static constexpr int TILE_J = 128;            // output cols per CTA
static constexpr int BROWS  = 2 * TILE_J;     // 256 w-rows (gate/up interleaved)
static constexpr int TILE_K = 64;             // fp16 -> 128B rows
static constexpr int STAGES = 4;
static constexpr int NITER  = HDIM / TILE_K;  // 64
static constexpr int MT     = MG / TILE_M;    // 16
static constexpr int NT     = IDIM / TILE_J;  // 12

static constexpr int A_BYTES     = TILE_M * TILE_K * 2;   // 16 KB
static constexpr int B_BYTES     = BROWS  * TILE_K * 2;   // 32 KB
static constexpr int STAGE_BYTES = A_BYTES + B_BYTES;     // 48 KB
static constexpr int SMEM_TOTAL  = STAGES * STAGE_BYTES;  // 192 KB
static constexpr int THREADS     = 256;                   // 8 warps: 2m x 4n

// ---------------- scratch: fp16 (RN) copies of inputs ----------------
__device__ __half g_xh[(size_t)MTOT * HDIM];               // 128 MB
__device__ __half g_wh[(size_t)GQ * 2 * IDIM * HDIM];      // 192 MB

// ---------------- PTX helpers (base sm_103: no tcgen05) ----------------
__device__ __forceinline__ uint32_t smem_u32(const void* p) {
    uint32_t a;
    asm("{ .reg .u64 t; cvta.to.shared.u64 t, %1; cvt.u32.u64 %0, t; }" : "=r"(a) : "l"(p));
    return a;
}
__device__ __forceinline__ void cp_async16(uint32_t dst, const void* src) {
    asm volatile("cp.async.cg.shared.global [%0], [%1], 16;" :: "r"(dst), "l"(src));
}
__device__ __forceinline__ void cp_commit() {
    asm volatile("cp.async.commit_group;" ::: "memory");
}
__device__ __forceinline__ void cp_wait1() {
    asm volatile("cp.async.wait_group 1;" ::: "memory");
}
__device__ __forceinline__ void ldsm4(uint32_t* r, uint32_t addr) {
    asm volatile("ldmatrix.sync.aligned.m8n8.x4.shared.b16 {%0,%1,%2,%3}, [%4];"
                 : "=r"(r[0]), "=r"(r[1]), "=r"(r[2]), "=r"(r[3]) : "r"(addr));
}
// fp16 MMA, fp32 accumulate: m16n8k16
__device__ __forceinline__ void mma16(float* d, const uint32_t* a, uint32_t b0, uint32_t b1) {
    asm volatile(
        "mma.sync.aligned.m16n8k16.row.col.f32.f16.f16.f32 "
        "{%0,%1,%2,%3}, {%4,%5,%6,%7}, {%8,%9}, {%0,%1,%2,%3};"
        : "+f"(d[0]), "+f"(d[1]), "+f"(d[2]), "+f"(d[3])
        : "r"(a[0]), "r"(a[1]), "r"(a[2]), "r"(a[3]), "r"(b0), "r"(b1));
}
__device__ __forceinline__ float silu_mul(float g, float u) {
    return g * u / (1.0f + __expf(-g));
}

// ---------------- prepass: fp32 -> fp16 (RN), both tensors in ONE kernel ----------------
__global__ void cvt_f16_kernel(const float4* __restrict__ x, __half* __restrict__ xh, int nx4,
                               const float4* __restrict__ w, __half* __restrict__ wh, int nw4) {
    int i = blockIdx.x * blockDim.x + threadIdx.x;
    const int stride = gridDim.x * blockDim.x;
    const int ntot = nx4 + nw4;
    for (; i < ntot; i += stride) {
        float4 v;
        __half* dst;
        if (i < nx4) { v = x[i]; dst = xh + (size_t)i * 4; }
        else         { v = w[i - nx4]; dst = wh + (size_t)(i - nx4) * 4; }
        __half2 lo = __floats2half2_rn(v.x, v.y);
        __half2 hi = __floats2half2_rn(v.z, v.w);
        uint2 pk;
        pk.x = *reinterpret_cast<uint32_t*>(&lo);
        pk.y = *reinterpret_cast<uint32_t*>(&hi);
        *reinterpret_cast<uint2*>(dst) = pk;
    }
}

// ---------------- fused grouped GEMM + SwiGLU (fp16 in, fp32 accum) ----------------
__global__ void __launch_bounds__(THREADS, 1)
swiglu_kernel(const __half* __restrict__ x, const __half* __restrict__ w,
              float* __restrict__ out) {
    extern __shared__ char smem[];
    const uint32_t sb = smem_u32(smem);

    const int tid  = threadIdx.x;
    const int lane = tid & 31;
    const int wid  = tid >> 5;
    const int wm   = wid >> 2;   // 0..1 (64 m-rows)
    const int wn   = wid & 3;    // 0..3 (64 B-rows = 32 out-cols)

    const int bx = blockIdx.x;
    const int g  = bx / (MT * NT);
    const int r2 = bx % (MT * NT);
    const int mt = r2 / NT;
    const int nt = r2 % NT;

    const size_t m0 = (size_t)g * MG + (size_t)mt * TILE_M;
    const int    n0 = nt * TILE_J;

    const __half* Ax = x + m0 * HDIM;
    const __half* Wg = w + ((size_t)g * (2 * IDIM) + (size_t)n0) * HDIM;

    // ---- per-thread cp.async descriptors (swizzle verified R2; 16B seg = 8 halves) ----
    uint32_t dA[4], oA[4];
    #pragma unroll
    for (int t = 0; t < 4; ++t) {
        const int c = tid + THREADS * t;     // 0..1023
        const int m = c >> 3, s = c & 7;
        dA[t] = (uint32_t)((((m >> 3) * 8 + s) << 7) + (((m & 7) ^ s) << 4));
        oA[t] = (uint32_t)(m * HDIM + s * 8);
    }
    uint32_t dB[8], oB[8];
    #pragma unroll
    for (int t = 0; t < 8; ++t) {
        const int c  = tid + THREADS * t;    // 0..2047
        const int rr = c >> 3, s = c & 7;
        const int j  = rr >> 1;              // even = gate j, odd = up j
        dB[t] = (uint32_t)(A_BYTES + (((rr >> 3) * 8 + s) << 7) + (((rr & 7) ^ s) << 4));
        oB[t] = (uint32_t)(j * HDIM + s * 8 + ((rr & 1) ? IDIM * HDIM : 0));
    }

    // ---- per-lane ldmatrix terms (identical structure to verified R2) ----
    const int quad = lane >> 3;
    const int row  = lane & 7;
    // A frag m16k16: quad -> (m-half = quad&1, k8-half = quad>>1)
    const uint32_t mterm0 = (uint32_t)((wm * 8 + (quad & 1)) << 10);
    uint32_t ktA[4];
    #pragma unroll
    for (int ks = 0; ks < 4; ++ks) {         // 4 x k16 steps per K=64 tile
        const int kb = 2 * ks + (quad >> 1); // 16B seg index 0..7
        ktA[ks] = (uint32_t)((kb << 7) + ((row ^ kb) << 4));
    }
    // B frag n8k16: quad -> (n-block = quad>>1, k8-half = quad&1)
    const uint32_t nterm0 = (uint32_t)(A_BYTES + ((wn * 8 + (quad >> 1)) << 10));
    uint32_t ktB[4];
    #pragma unroll
    for (int ks = 0; ks < 4; ++ks) {
        const int kb = 2 * ks + (quad & 1);
        ktB[ks] = (uint32_t)((kb << 7) + ((row ^ kb) << 4));
    }

    float acc[128];
    #pragma unroll
    for (int i = 0; i < 128; ++i) acc[i] = 0.0f;

    // ---- prologue: fill stages 0..2 ----
    #pragma unroll
    for (int s = 0; s < STAGES - 1; ++s) {
        const uint32_t st = sb + (uint32_t)(s * STAGE_BYTES);
        const __half* a = Ax + s * TILE_K;
        const __half* b = Wg + s * TILE_K;
        #pragma unroll
        for (int t = 0; t < 4; ++t) cp_async16(st + dA[t], a + oA[t]);
        #pragma unroll
        for (int t = 0; t < 8; ++t) cp_async16(st + dB[t], b + oB[t]);
        cp_commit();
    }

    // ---- mainloop ----
    #pragma unroll 1
    for (int i = 0; i < NITER; ++i) {
        cp_wait1();          // stages <= i+1 resident (own warp's copies)
        __syncthreads();     // cross-warp visibility; stage i-1 reads complete

        if (i + STAGES - 1 < NITER) {
            const int it = i + STAGES - 1;
            const uint32_t stw = sb + (uint32_t)((it & 3) * STAGE_BYTES);
            const __half* a = Ax + it * TILE_K;
            const __half* b = Wg + it * TILE_K;
            #pragma unroll
            for (int t = 0; t < 4; ++t) cp_async16(stw + dA[t], a + oA[t]);
            #pragma unroll
            for (int t = 0; t < 8; ++t) cp_async16(stw + dB[t], b + oB[t]);
        }
        cp_commit();

        const uint32_t st = sb + (uint32_t)((i & 3) * STAGE_BYTES);
        #pragma unroll
        for (int ks = 0; ks < 4; ++ks) {
            uint32_t afr[16], bfr[16];
            #pragma unroll
            for (int f = 0; f < 4; ++f)      // 4 m16-frags (64 rows)
                ldsm4(&afr[4 * f], st + mterm0 + (uint32_t)(f << 11) + ktA[ks]);
            #pragma unroll
            for (int gg = 0; gg < 4; ++gg)   // 8 n8-frags (64 B-rows)
                ldsm4(&bfr[4 * gg], st + nterm0 + (uint32_t)(gg << 11) + ktB[ks]);
            #pragma unroll
            for (int f = 0; f < 4; ++f) {
                #pragma unroll
                for (int nf = 0; nf < 8; ++nf) {
                    const int bo = ((nf >> 1) << 2) + ((nf & 1) << 1);
                    mma16(&acc[(f * 8 + nf) * 4], &afr[4 * f], bfr[bo], bfr[bo + 1]);
                }
            }
        }
    }

    __syncthreads();

    // ---- epilogue: silu(gate)*up, direct global stores ----
    const int gid = lane >> 2;
    const int tg  = lane & 3;
    #pragma unroll
    for (int f = 0; f < 4; ++f) {
        #pragma unroll
        for (int nf = 0; nf < 8; ++nf) {
            const float* c = &acc[(f * 8 + nf) * 4];
            const size_t mg1 = m0 + (size_t)(wm * 64 + f * 16 + gid);
            const int    jg  = n0 + wn * 32 + nf * 4 + tg;
            out[mg1 * IDIM + jg]       = silu_mul(c[0], c[1]);
            out[(mg1 + 8) * IDIM + jg] = silu_mul(c[2], c[3]);
        }
    }
}

// ---------------- launch ----------------
extern "C" void kernel_launch(void* const* d_in, const int* in_sizes, int n_in,
                              void* d_out, int out_size) {
    const float* x = (const float*)d_in[0];
    const float* w = (const float*)d_in[1];
    float* out = (float*)d_out;

    void* pxh = nullptr;
    void* pwh = nullptr;
    cudaGetSymbolAddress(&pxh, g_xh);
    cudaGetSymbolAddress(&pwh, g_wh);

    const int nx4 = (int)(((size_t)MTOT * HDIM) / 4);
    const int nw4 = (int)(((size_t)GQ * 2 * IDIM * HDIM) / 4);
    cvt_f16_kernel<<<2048, 256>>>((const float4*)x, (__half*)pxh, nx4,
                                  (const float4*)w, (__half*)pwh, nw4);

    cudaFuncSetAttribute(swiglu_kernel,
                         cudaFuncAttributeMaxDynamicSharedMemorySize, SMEM_TOTAL);
    swiglu_kernel<<<GQ * MT * NT, THREADS, SMEM_TOTAL>>>(
        (const __half*)pxh, (const __half*)pwh, out);
}